// round 1
// baseline (speedup 1.0000x reference)
#include <cuda_runtime.h>
#include <math.h>

#define NN 20000
#define EE 80000
#define GG 1000
#define FTOT 16
#define CSD 5
#define FCIN 75

// ---------------- device scratch (allocation-free contract) ----------------
__device__ float g_hA[NN * 64];
__device__ float g_hB[NN * 64];
__device__ float g_hid[(size_t)EE * 128];
__device__ float g_P[(size_t)NN * 128 * 64];   // 625 MB, max layer
__device__ float g_R[NN * 64];
__device__ float g_agg[NN * 64];
__device__ float g_gsum[GG * FCIN];
__device__ float g_gcnt[GG];

__device__ __forceinline__ float* hbuf(int s) { return s ? g_hB : g_hA; }
__device__ __forceinline__ float elu_f(float x) { return x > 0.f ? x : (expf(x) - 1.f); }

// ---------------- kernels ----------------

// h0[n,i] = x[n,i], i < 5
__global__ void init_h0_kernel(const float* __restrict__ x) {
    int idx = blockIdx.x * blockDim.x + threadIdx.x;
    if (idx >= NN * CSD) return;
    int n = idx / CSD, i = idx % CSD;
    g_hA[n * CSD + i] = x[n * FTOT + i];
}

// hid[e,k] = relu(b1[k] + sum_a ea[e,a]*w1[a,k]); one block per edge, 128 threads
__global__ void hid_kernel(const float* __restrict__ ea,
                           const float* __restrict__ w1,
                           const float* __restrict__ b1) {
    int e = blockIdx.x;
    int k = threadIdx.x;
    __shared__ float a[5];
    if (k < 5) a[k] = ea[e * 5 + k];
    __syncthreads();
    float s = b1[k];
#pragma unroll
    for (int i = 0; i < 5; i++) s = fmaf(a[i], w1[i * 128 + k], s);
    g_hid[(size_t)e * 128 + k] = fmaxf(s, 0.f);
}

// P[n, k*MO+o] = sum_i h[n,i] * w2[k*MI*MO + i*MO + o]
// tiled GEMM: 32 nodes x 64 cols per block, 128 threads, 4x4 microtile
template <int MI, int MO>
__global__ __launch_bounds__(128) void p_kernel(const float* __restrict__ w2, int insel) {
    const int COLS = 128 * MO;
    __shared__ float As[32][MI + 1];
    __shared__ float Bs[MI][64];
    const float* h = hbuf(insel);
    int nb = blockIdx.y * 32;
    int cb = blockIdx.x * 64;
    int t = threadIdx.x;

    for (int idx = t; idx < 32 * MI; idx += 128) {
        int n = idx / MI, i = idx % MI;
        As[n][i] = (nb + n < NN) ? h[(nb + n) * MI + i] : 0.f;
    }
    for (int idx = t; idx < MI * 64; idx += 128) {
        int i = idx / 64, c = idx % 64;
        int cg = cb + c;
        int k = cg / MO, o = cg % MO;
        Bs[i][c] = w2[k * MI * MO + i * MO + o];
    }
    __syncthreads();

    int cr = (t & 15) * 4;
    int nr = (t >> 4) * 4;
    float acc[4][4];
#pragma unroll
    for (int r = 0; r < 4; r++)
#pragma unroll
        for (int c = 0; c < 4; c++) acc[r][c] = 0.f;

#pragma unroll
    for (int i = 0; i < MI; i++) {
        float a0 = As[nr + 0][i], a1 = As[nr + 1][i], a2 = As[nr + 2][i], a3 = As[nr + 3][i];
        float b0 = Bs[i][cr + 0], b1 = Bs[i][cr + 1], b2 = Bs[i][cr + 2], b3 = Bs[i][cr + 3];
        acc[0][0] = fmaf(a0, b0, acc[0][0]); acc[0][1] = fmaf(a0, b1, acc[0][1]);
        acc[0][2] = fmaf(a0, b2, acc[0][2]); acc[0][3] = fmaf(a0, b3, acc[0][3]);
        acc[1][0] = fmaf(a1, b0, acc[1][0]); acc[1][1] = fmaf(a1, b1, acc[1][1]);
        acc[1][2] = fmaf(a1, b2, acc[1][2]); acc[1][3] = fmaf(a1, b3, acc[1][3]);
        acc[2][0] = fmaf(a2, b0, acc[2][0]); acc[2][1] = fmaf(a2, b1, acc[2][1]);
        acc[2][2] = fmaf(a2, b2, acc[2][2]); acc[2][3] = fmaf(a2, b3, acc[2][3]);
        acc[3][0] = fmaf(a3, b0, acc[3][0]); acc[3][1] = fmaf(a3, b1, acc[3][1]);
        acc[3][2] = fmaf(a3, b2, acc[3][2]); acc[3][3] = fmaf(a3, b3, acc[3][3]);
    }
#pragma unroll
    for (int r = 0; r < 4; r++) {
        int n = nb + nr + r;
        if (n < NN) {
#pragma unroll
            for (int c = 0; c < 4; c++)
                g_P[(size_t)n * COLS + (cb + cr + c)] = acc[r][c];
        }
    }
}

// R[n,o] = sum_i h[n,i]*b2[i*MO+o]   (b2 contribution through the einsum)
template <int MI, int MO>
__global__ void r_kernel(const float* __restrict__ b2, int insel) {
    int idx = blockIdx.x * blockDim.x + threadIdx.x;
    if (idx >= NN * MO) return;
    int n = idx / MO, o = idx % MO;
    const float* h = hbuf(insel);
    float s = 0.f;
#pragma unroll
    for (int i = 0; i < MI; i++) s = fmaf(h[n * MI + i], b2[i * MO + o], s);
    g_R[n * MO + o] = s;
}

__global__ void zero_agg_kernel() {
    int idx = blockIdx.x * blockDim.x + threadIdx.x;
    if (idx < NN * 64) g_agg[idx] = 0.f;
}

// msg[e,o] = R[src,o] + sum_k hid[e,k]*P[src,k*MO+o]; atomic scatter to agg[dst]
template <int MO>
__global__ __launch_bounds__(256) void edge_kernel(const int* __restrict__ ei) {
    const int EPB = 256 / MO;
    const int COLSP = 128 * MO;
    __shared__ float hs[EPB][128];
    __shared__ int ssrc[EPB], sdst[EPB];
    int t = threadIdx.x;
    int e0 = blockIdx.x * EPB;
    for (int idx = t; idx < EPB * 128; idx += 256) {
        int le = idx >> 7, k = idx & 127;
        hs[le][k] = g_hid[(size_t)(e0 + le) * 128 + k];
    }
    if (t < EPB) {
        ssrc[t] = ei[e0 + t];
        sdst[t] = ei[EE + e0 + t];
    }
    __syncthreads();
    int le = t / MO, o = t % MO;
    int src = ssrc[le], dst = sdst[le];
    const float* Pp = &g_P[(size_t)src * COLSP + o];
    float acc = g_R[src * MO + o];
#pragma unroll 8
    for (int k = 0; k < 128; k++) acc = fmaf(hs[le][k], Pp[(size_t)k * MO], acc);
    atomicAdd(&g_agg[dst * MO + o], acc);
}

// h_out[n,o] = elu(agg[n,o] + sum_i h_in[n,i]*root[i,o] + bias[o])
template <int MI, int MO>
__global__ void root_kernel(const float* __restrict__ root,
                            const float* __restrict__ bias,
                            int insel, int outsel) {
    int n = blockIdx.x;
    int o = threadIdx.x;  // MO threads
    __shared__ float hr[64];
    const float* hin = hbuf(insel);
    if (o < MI) hr[o] = hin[n * MI + o];
    __syncthreads();
    float s = g_agg[n * MO + o] + bias[o];
#pragma unroll
    for (int i = 0; i < MI; i++) s = fmaf(hr[i], root[i * MO + o], s);
    hbuf(outsel)[n * MO + o] = elu_f(s);
}

__global__ void zero_pool_kernel() {
    int idx = blockIdx.x * blockDim.x + threadIdx.x;
    if (idx < GG * FCIN) g_gsum[idx] = 0.f;
    if (idx < GG) g_gcnt[idx] = 0.f;
}

__global__ void pool_scatter_kernel(const float* __restrict__ x,
                                    const int* __restrict__ batch, int hsel) {
    int idx = blockIdx.x * blockDim.x + threadIdx.x;
    if (idx >= NN * FCIN) return;
    int n = idx / FCIN, d = idx % FCIN;
    const float* h = hbuf(hsel);
    float v = (d < 64) ? h[n * 64 + d] : x[n * FTOT + CSD + (d - 64)];
    int b = batch[n];
    atomicAdd(&g_gsum[b * FCIN + d], v);
    if (d == 0) atomicAdd(&g_gcnt[b], 1.f);
}

__global__ void mlp_kernel(const float* __restrict__ fc1w, const float* __restrict__ fc1b,
                           const float* __restrict__ fc2w, const float* __restrict__ fc2b,
                           const float* __restrict__ fc3w, const float* __restrict__ fc3b,
                           float* __restrict__ out) {
    int g = blockIdx.x;
    int t = threadIdx.x;  // 32
    __shared__ float gv[FCIN], a1[32], a2[16];
    float cnt = fmaxf(g_gcnt[g], 1.f);
    for (int i = t; i < FCIN; i += 32) gv[i] = g_gsum[g * FCIN + i] / cnt;
    __syncthreads();
    {
        float s = fc1b[t];
        for (int i = 0; i < FCIN; i++) s = fmaf(gv[i], fc1w[i * 32 + t], s);
        a1[t] = elu_f(s);
    }
    __syncthreads();
    if (t < 16) {
        float s = fc2b[t];
#pragma unroll
        for (int i = 0; i < 32; i++) s = fmaf(a1[i], fc2w[i * 16 + t], s);
        a2[t] = elu_f(s);
    }
    __syncthreads();
    if (t == 0) {
        float s = fc3b[0];
#pragma unroll
        for (int i = 0; i < 16; i++) s = fmaf(a2[i], fc3w[i], s);
        out[g] = s;
    }
}

// ---------------- host side ----------------

template <int MI, int MO>
static void run_layer(const float* ea, const int* ei,
                      const float* w1, const float* b1,
                      const float* w2, const float* b2,
                      const float* root, const float* bias,
                      int insel, int outsel) {
    hid_kernel<<<EE, 128>>>(ea, w1, b1);
    dim3 pg((128 * MO) / 64, (NN + 31) / 32);
    p_kernel<MI, MO><<<pg, 128>>>(w2, insel);
    r_kernel<MI, MO><<<(NN * MO + 255) / 256, 256>>>(b2, insel);
    zero_agg_kernel<<<(NN * 64 + 255) / 256, 256>>>();
    edge_kernel<MO><<<EE / (256 / MO), 256>>>(ei);
    root_kernel<MI, MO><<<NN, MO>>>(root, bias, insel, outsel);
}

extern "C" void kernel_launch(void* const* d_in, const int* in_sizes, int n_in,
                              void* d_out, int out_size) {
    const float* x  = (const float*)d_in[0];
    const int*   ei = (const int*)d_in[1];
    const float* ea = (const float*)d_in[2];
    const int*   batch = (const int*)d_in[3];

    const float* c1w1 = (const float*)d_in[4];
    const float* c1b1 = (const float*)d_in[5];
    const float* c1w2 = (const float*)d_in[6];
    const float* c1b2 = (const float*)d_in[7];
    const float* c1root = (const float*)d_in[8];
    const float* c1bias = (const float*)d_in[9];

    const float* c2w1 = (const float*)d_in[10];
    const float* c2b1 = (const float*)d_in[11];
    const float* c2w2 = (const float*)d_in[12];
    const float* c2b2 = (const float*)d_in[13];
    const float* c2root = (const float*)d_in[14];
    const float* c2bias = (const float*)d_in[15];

    const float* c3w1 = (const float*)d_in[16];
    const float* c3b1 = (const float*)d_in[17];
    const float* c3w2 = (const float*)d_in[18];
    const float* c3b2 = (const float*)d_in[19];
    const float* c3root = (const float*)d_in[20];
    const float* c3bias = (const float*)d_in[21];

    const float* fc1w = (const float*)d_in[22];
    const float* fc1b = (const float*)d_in[23];
    const float* fc2w = (const float*)d_in[24];
    const float* fc2b = (const float*)d_in[25];
    const float* fc3w = (const float*)d_in[26];
    const float* fc3b = (const float*)d_in[27];

    init_h0_kernel<<<(NN * CSD + 255) / 256, 256>>>(x);

    // layer 1: 5 -> 32   (h in A, out B)
    run_layer<5, 32>(ea, ei, c1w1, c1b1, c1w2, c1b2, c1root, c1bias, 0, 1);
    // layer 2: 32 -> 64  (h in B, out A)
    run_layer<32, 64>(ea, ei, c2w1, c2b1, c2w2, c2b2, c2root, c2bias, 1, 0);
    // layer 3: 64 -> 64  (h in A, out B)
    run_layer<64, 64>(ea, ei, c3w1, c3b1, c3w2, c3b2, c3root, c3bias, 0, 1);

    zero_pool_kernel<<<(GG * FCIN + 255) / 256, 256>>>();
    pool_scatter_kernel<<<(NN * FCIN + 255) / 256, 256>>>(x, batch, 1);
    mlp_kernel<<<GG, 32>>>(fc1w, fc1b, fc2w, fc2b, fc3w, fc3b, (float*)d_out);
}